// round 7
// baseline (speedup 1.0000x reference)
#include <cuda_runtime.h>

#define BATCH 64
#define NN 512
#define NDIAG 1023
#define NEGV  (-1e30f)
#define INV_LN2 1.44269504088896340736f
#define LN2F    0.69314718055994530942f
#define NWARP 4                      // warps per DP CTA
#define DD 8                         // diagonals per round
#define NROUNDS (128 + NWARP - 1)    // 131
#define CADDR (1022 * NN + 511)      // bwd mirror: addr = CADDR - (k*NN + i)

// Diagonal-major layout: (k, i) -> k*NN + i, valid i in [max(0,k-511), min(511,k)].
__device__ float g_ddiag[(size_t)BATCH * NDIAG * NN];
__device__ float g_f[(size_t)BATCH * NDIAG * NN];
__device__ float g_b[(size_t)BATCH * NDIAG * NN];
__device__ unsigned int g_maxu;

__device__ __forceinline__ float ex2f(float x) {
    float y; asm("ex2.approx.ftz.f32 %0, %1;" : "=f"(y) : "f"(x)); return y;
}
__device__ __forceinline__ float lg2f(float x) {
    float y; asm("lg2.approx.ftz.f32 %0, %1;" : "=f"(y) : "f"(x)); return y;
}
__device__ __forceinline__ unsigned int fenc(float x) {
    unsigned int b = __float_as_uint(x);
    return (b & 0x80000000u) ? ~b : (b | 0x80000000u);
}
__device__ __forceinline__ float fdec(unsigned int u) {
    return __uint_as_float((u & 0x80000000u) ? (u & 0x7fffffffu) : ~u);
}

__global__ void init_max_kernel() { g_maxu = 0u; }

// ---------------------------------------------------------------------------
// Pre-pass: D (row-major) -> g_ddiag (diag-major), scaled by 1/ln2.
// ---------------------------------------------------------------------------
__global__ void __launch_bounds__(256) diagize_kernel(const float* __restrict__ D) {
    __shared__ float t[32][34];
    int b = blockIdx.z, i0 = blockIdx.y * 32, j0 = blockIdx.x * 32;
    const float* Db = D + (size_t)b * NN * NN;
    float* out = g_ddiag + (size_t)b * NDIAG * NN;
    int tid = threadIdx.x, lane = tid & 31, w = tid >> 5;
#pragma unroll
    for (int r = 0; r < 4; r++) {
        int il = w + 8 * r;
        t[il][lane] = Db[(size_t)(i0 + il) * NN + j0 + lane] * INV_LN2;
    }
    __syncthreads();
#pragma unroll
    for (int r = 0; r < 8; r++) {
        int ld = w + 8 * r;
        if (ld < 63) {
            int ilo = max(0, ld - 31);
            int il = ilo + lane;
            if (il <= min(31, ld)) {
                int k = i0 + j0 + ld;
                out[(size_t)k * NN + (i0 + il)] = t[il][ld - il];
            }
        }
    }
}

__device__ __forceinline__ float lse_cell(float dg, float up, float lf, float dcur) {
    float hi1 = fmaxf(dg, up);
    float lo1 = fminf(dg, up);
    float m   = fmaxf(hi1, lf);
    float o2  = fminf(hi1, lf);
    float s = ex2f(lo1 - m) + ex2f(o2 - m);   // third term is 2^0 = 1
    return dcur + m + lg2f(1.0f + s);
}

// Load 4 consecutive rows of diag k starting at i0 (fwd), or the mirrored
// addresses for bwd (components reversed).
template<bool BWD>
__device__ __forceinline__ float4 load4(const float* dd, int k, int i0) {
    if (!BWD) {
        return *(const float4*)(dd + (size_t)k * NN + i0);
    } else {
        float4 t = *(const float4*)(dd + (size_t)(CADDR - 3) - ((size_t)k * NN + i0));
        return make_float4(t.w, t.z, t.y, t.x);
    }
}

// ---------------------------------------------------------------------------
// Wavefront DP: 128 threads (4 warps, exactly 1 per SMSP). Thread t owns rows
// 4t..4t+3; warp w owns rows [128w, 128w+128) and lags warp w-1 by DD=8
// diagonals. Per diagonal: 1 shfl provides the cross-lane neighbor (last row
// of lane-1); rows 1..3 use in-register values. Cross-warp edge (row 128w-1)
// flows through a 32-slot smem ring, ordered by one __syncthreads per round.
// D loads are LDG.128 (8-deep in-place prefetch), stores are STG.128, both
// predicated to the thread's valid diagonal window [i0, i0+514].
// ---------------------------------------------------------------------------
template<bool BWD>
__device__ __forceinline__ void dp_impl(int b, float (*edge)[32]) {
    const float* dd = g_ddiag + (size_t)b * NDIAG * NN;
    float* out = (BWD ? g_b : g_f) + (size_t)b * NDIAG * NN;
    int tid = threadIdx.x, lane = tid & 31, w = tid >> 5;
    int i0 = 4 * tid;

    float v1[4] = {NEGV, NEGV, NEGV, NEGV};
    float v2[4] = {NEGV, NEGV, NEGV, NEGV};

    float4 pf[8];
#pragma unroll
    for (int q = 0; q < 8; q++) {
        pf[q] = make_float4(NEGV, NEGV, NEGV, NEGV);
        if (q >= i0) pf[q] = load4<BWD>(dd, q, i0);   // window lower bound
    }

    for (int r = 0; r < NROUNDS; r++) {
        int kbase = DD * (r - w);
        if (kbase >= 0 && kbase < NDIAG) {
            float e[9];
#pragma unroll
            for (int q = 0; q < 9; q++) {
                int kq = kbase - 2 + q;
                e[q] = (w > 0 && kq >= 0) ? edge[w - 1][kq & 31] : NEGV;
            }
            float sprev = __shfl_up_sync(0xffffffffu, v2[3], 1);
#pragma unroll
            for (int p = 0; p < 8; p++) {
                int k = kbase + p;
                float4 dc = pf[p];
                {   // in-place prefetch for diag k+8 (next round, same phase)
                    int kn = k + 8;
                    if (kn >= i0 && kn <= i0 + 514 && kn < NDIAG)
                        pf[p] = load4<BWD>(dd, kn, i0);
                }
                float s1 = __shfl_up_sync(0xffffffffu, v1[3], 1);
                float up0 = (lane == 0) ? e[p + 1] : s1;
                float dg0 = (lane == 0) ? e[p]     : sprev;
                float dcv[4] = {dc.x, dc.y, dc.z, dc.w};
                float nv[4];
#pragma unroll
                for (int m = 0; m < 4; m++) {
                    int i = i0 + m;
                    int j = k - i;
                    float up = (m == 0) ? up0 : v1[m - 1];
                    float dg = (m == 0) ? dg0 : v2[m - 1];
                    float lf = v1[m];
                    float dgx = (j == 0) ? ((i == 0) ? 0.0f : NEGV) : dg;
                    float lfx = (j == 0) ? NEGV : lf;
                    bool valid = (j >= 0) && (j < NN) && (k < NDIAG);
                    float val = lse_cell(dgx, up, lfx, dcv[m]);
                    nv[m] = valid ? val : NEGV;
                }
#pragma unroll
                for (int m = 0; m < 4; m++) { v2[m] = v1[m]; v1[m] = nv[m]; }
                if (k >= i0 && k <= i0 + 514 && k < NDIAG)
                    *(float4*)(out + (size_t)k * NN + i0) =
                        make_float4(nv[0], nv[1], nv[2], nv[3]);
                if (lane == 31) edge[w][k & 31] = nv[3];
                sprev = s1;
            }
        }
        __syncthreads();   // publishes edge writes to the warp below
    }
}

__global__ void __launch_bounds__(128) dp_kernel() {
    __shared__ float edge[NWARP][32];
    int bx = blockIdx.x;
    int b = bx >> 1, dir = bx & 1;
    if (dir) dp_impl<true>(b, edge);
    else     dp_impl<false>(b, edge);
}

// ---------------------------------------------------------------------------
// Combine: logit2 = f2 + b2 - d2, de-diagonalize to row-major out,
// per-block max -> encoded atomicMax.
// ---------------------------------------------------------------------------
__global__ void __launch_bounds__(256) combine_kernel(float* __restrict__ out) {
    __shared__ float tile[32][257];
    __shared__ float smax[8];
    int b = blockIdx.y;
    int k0 = blockIdx.x * 32;
    const float* fd = g_f + (size_t)b * NDIAG * NN;
    const float* bd = g_b + (size_t)b * NDIAG * NN;
    const float* dd = g_ddiag + (size_t)b * NDIAG * NN;
    float* ob = out + (size_t)b * NN * NN;
    int tid = threadIdx.x, lane = tid & 31, w = tid >> 5;
    float vmax = -3.4e38f;

    for (int ih = 0; ih < 2; ih++) {
        int ibase = ih * 256;
        for (int kk = 0; kk < 32; kk++) {
            int k = k0 + kk;
            int i = ibase + tid;
            int j = k - i;
            float v = 0.0f;
            if (j >= 0 && j < NN) {
                int a = k * NN + i;
                v = fd[a] + bd[(1022 - k) * NN + (511 - i)] - dd[a];
                vmax = fmaxf(vmax, v);
            }
            tile[kk][tid] = v;
        }
        __syncthreads();
        for (int rr = 0; rr < 32; rr++) {
            int i = ibase + w * 32 + rr;
            int jlo = max(0, k0 - i);
            int jhi = min(NN - 1, k0 + 31 - i);
            int j = jlo + lane;
            if (j <= jhi) {
                int kk = i + j - k0;
                ob[(size_t)i * NN + j] = tile[kk][i - ibase];
            }
        }
        __syncthreads();
    }

#pragma unroll
    for (int o = 16; o > 0; o >>= 1)
        vmax = fmaxf(vmax, __shfl_xor_sync(0xffffffffu, vmax, o));
    if (lane == 0) smax[w] = vmax;
    __syncthreads();
    if (tid == 0) {
        float v = smax[0];
#pragma unroll
        for (int q = 1; q < 8; q++) v = fmaxf(v, smax[q]);
        atomicMax(&g_maxu, fenc(v));
    }
}

__global__ void __launch_bounds__(256) finish_kernel(float* __restrict__ out, int n4) {
    float mx = fdec(g_maxu);
    float4* o4 = (float4*)out;
    int idx = blockIdx.x * blockDim.x + threadIdx.x;
    int stride = gridDim.x * blockDim.x;
    for (int t = idx; t < n4; t += stride) {
        float4 v = o4[t];
        v.x = (v.x - mx) * LN2F;
        v.y = (v.y - mx) * LN2F;
        v.z = (v.z - mx) * LN2F;
        v.w = (v.w - mx) * LN2F;
        o4[t] = v;
    }
}

extern "C" void kernel_launch(void* const* d_in, const int* in_sizes, int n_in,
                              void* d_out, int out_size) {
    const float* d = (const float*)d_in[0];
    float* out = (float*)d_out;

    init_max_kernel<<<1, 1>>>();

    dim3 dgrid(16, 16, BATCH);
    diagize_kernel<<<dgrid, 256>>>(d);

    dp_kernel<<<BATCH * 2, 128>>>();

    dim3 cgrid(32, BATCH);
    combine_kernel<<<cgrid, 256>>>(out);

    finish_kernel<<<4096, 256>>>(out, out_size / 4);
}

// round 8
// speedup vs baseline: 1.3148x; 1.3148x over previous
#include <cuda_runtime.h>

#define BATCH 64
#define NN 512
#define NDIAG 1023
#define NEGV  (-1e30f)
#define INV_LN2 1.44269504088896340736f
#define LN2F    0.69314718055994530942f
#define TS (NN + 1)
#define CADDR (1022 * NN + 511)

// Diagonal-major layout: (k, i) -> k*NN + i, valid i in [max(0,k-511), min(511,k)].
__device__ float g_ddiag[(size_t)BATCH * NDIAG * NN];  // D / ln2
__device__ float g_f[(size_t)BATCH * NDIAG * NN];      // forward DP (log2 domain)
__device__ float g_b[(size_t)BATCH * NDIAG * NN];      // backward DP MINUS d (log2)
__device__ float g_max;                                // global logit max (log2)

__device__ __forceinline__ float ex2f(float x) {
    float y; asm("ex2.approx.ftz.f32 %0, %1;" : "=f"(y) : "f"(x)); return y;
}
__device__ __forceinline__ float lg2f(float x) {
    float y; asm("lg2.approx.ftz.f32 %0, %1;" : "=f"(y) : "f"(x)); return y;
}

// ---------------------------------------------------------------------------
// Pre-pass: D (row-major) -> g_ddiag (diag-major), scaled by 1/ln2.
// ---------------------------------------------------------------------------
__global__ void __launch_bounds__(256) diagize_kernel(const float* __restrict__ D) {
    __shared__ float t[32][34];
    int b = blockIdx.z, i0 = blockIdx.y * 32, j0 = blockIdx.x * 32;
    const float* Db = D + (size_t)b * NN * NN;
    float* out = g_ddiag + (size_t)b * NDIAG * NN;
    int tid = threadIdx.x, lane = tid & 31, w = tid >> 5;
#pragma unroll
    for (int r = 0; r < 4; r++) {
        int il = w + 8 * r;
        t[il][lane] = Db[(size_t)(i0 + il) * NN + j0 + lane] * INV_LN2;
    }
    __syncthreads();
#pragma unroll
    for (int r = 0; r < 8; r++) {
        int ld = w + 8 * r;
        if (ld < 63) {
            int ilo = max(0, ld - 31);
            int il = ilo + lane;
            if (il <= min(31, ld)) {
                int k = i0 + j0 + ld;
                out[(size_t)k * NN + (i0 + il)] = t[il][ld - il];
            }
        }
    }
}

__device__ __forceinline__ float lse_cell(float dg, float up, float lf, float dcur) {
    float hi1 = fmaxf(dg, up);
    float lo1 = fminf(dg, up);
    float m   = fmaxf(hi1, lf);
    float o2  = fminf(hi1, lf);
    float s = ex2f(lo1 - m) + ex2f(o2 - m);   // third term is 2^0 = 1
    return dcur + m + lg2f(1.0f + s);
}

// ---------------------------------------------------------------------------
// Wavefront DP, one CTA per batch, BOTH directions in one 1024-thread CTA:
// threads [0,512) = forward, [512,1024) = backward (independent smem bufs,
// shared per-diagonal barrier). This amortizes barrier/issue-bubble overhead
// over 2 problems while MUFU totals per diagonal are unchanged.
// k-loop unrolled x8 keeps the 8-deep LDG prefetch pipeline real; 4 rotating
// smem buffers make the selector compile-time static.
// Backward half writes (val - d) so combine never needs to re-read d.
// ---------------------------------------------------------------------------
__global__ void __launch_bounds__(1024) dp_kernel() {
    __shared__ float bufs[2][4][TS];   // [half][rot][row]; slot [.][.][0] = boundary
    int b = blockIdx.x;
    int half = threadIdx.x >> 9;       // 0 = fwd, 1 = bwd
    int i = threadIdx.x & 511;

    const float* dd = g_ddiag + (size_t)b * NDIAG * NN;
    float* out = (half ? g_b : g_f) + (size_t)b * NDIAG * NN;

    if (i < 4) bufs[half][i][0] = NEGV;
    __syncthreads();

    float pf[8];
#pragma unroll
    for (int q = 0; q < 8; q++) {
        int base = q * NN + i;
        pf[q] = dd[half ? (CADDR - base) : base];
    }

    for (int t = 0; t < 128; t++) {
#pragma unroll
        for (int p = 0; p < 8; p++) {
            int k = t * 8 + p;                 // k==1023 is a no-op pad
            float dcur = pf[p];
            {
                int kn = k + 8; if (kn > NDIAG - 1) kn = NDIAG - 1;
                int base = kn * NN + i;
                pf[p] = dd[half ? (CADDR - base) : base];
            }
            if (k < NDIAG) {                   // uniform over the block
                float* bc  = &bufs[half][p & 3][1];        // diag k
                float* b1p = &bufs[half][(p + 3) & 3][1];  // diag k-1
                float* b2p = &bufs[half][(p + 2) & 3][1];  // diag k-2
                int j = k - i;
                if (j >= 0 && j < NN) {
                    float dg = (j == 0) ? ((i == 0) ? 0.0f : NEGV) : b2p[i - 1];
                    float up = b1p[i - 1];                 // i==0 -> boundary
                    float lf = (j == 0) ? NEGV : b1p[i];
                    float val = lse_cell(dg, up, lf, dcur);
                    bc[i] = val;
                    out[(size_t)k * NN + i] = half ? (val - dcur) : val;
                }
                __syncthreads();
            }
        }
    }
}

// ---------------------------------------------------------------------------
// Global max: logit(i,j) <= logit(N-1,M-1) = f(N-1,M-1) (corner lies on every
// path), so max = max_b f_b[diag 1022, i=511]. 64 loads, one warp.
// ---------------------------------------------------------------------------
__global__ void max_kernel() {
    int t = threadIdx.x;   // 32 threads
    float m = -3.4e38f;
    for (int b = t; b < BATCH; b += 32)
        m = fmaxf(m, g_f[(size_t)b * NDIAG * NN + (size_t)1022 * NN + 511]);
#pragma unroll
    for (int o = 16; o > 0; o >>= 1)
        m = fmaxf(m, __shfl_xor_sync(0xffffffffu, m, o));
    if (t == 0) g_max = m;
}

// ---------------------------------------------------------------------------
// Combine + finish fused: out = (f2 + (b2-d2) - max2) * ln2, de-diagonalized
// to row-major via a padded smem tile. No d read, no second output pass.
// ---------------------------------------------------------------------------
__global__ void __launch_bounds__(256) combine_kernel(float* __restrict__ out) {
    __shared__ float tile[32][257];
    int b = blockIdx.y;
    int k0 = blockIdx.x * 32;
    const float* fd = g_f + (size_t)b * NDIAG * NN;
    const float* bd = g_b + (size_t)b * NDIAG * NN;
    float* ob = out + (size_t)b * NN * NN;
    int tid = threadIdx.x, lane = tid & 31, w = tid >> 5;
    float mx = g_max;

    for (int ih = 0; ih < 2; ih++) {
        int ibase = ih * 256;
        for (int kk = 0; kk < 32; kk++) {
            int k = k0 + kk;
            int i = ibase + tid;
            int j = k - i;
            float v = 0.0f;
            if (j >= 0 && j < NN) {
                int a = k * NN + i;
                v = (fd[a] + bd[(1022 - k) * NN + (511 - i)] - mx) * LN2F;
            }
            tile[kk][tid] = v;
        }
        __syncthreads();
        for (int rr = 0; rr < 32; rr++) {
            int i = ibase + w * 32 + rr;
            int jlo = max(0, k0 - i);
            int jhi = min(NN - 1, k0 + 31 - i);
            int j = jlo + lane;
            if (j <= jhi) {
                int kk = i + j - k0;
                ob[(size_t)i * NN + j] = tile[kk][i - ibase];
            }
        }
        __syncthreads();
    }
}

extern "C" void kernel_launch(void* const* d_in, const int* in_sizes, int n_in,
                              void* d_out, int out_size) {
    const float* d = (const float*)d_in[0];
    float* out = (float*)d_out;

    dim3 dgrid(16, 16, BATCH);
    diagize_kernel<<<dgrid, 256>>>(d);

    dp_kernel<<<BATCH, 1024>>>();

    max_kernel<<<1, 32>>>();

    dim3 cgrid(32, BATCH);
    combine_kernel<<<cgrid, 256>>>(out);
}

// round 9
// speedup vs baseline: 1.4672x; 1.1159x over previous
#include <cuda_runtime.h>

#define BATCH 64
#define NN 512
#define NDIAG 1023
#define NEGV  (-1e30f)
#define INV_LN2 1.44269504088896340736f
#define LN2F    0.69314718055994530942f
#define TS (NN + 1)
#define CADDR (1022 * NN + 511)

// Diagonal-major layout: (k, i) -> k*NN + i, valid i in [max(0,k-511), min(511,k)].
__device__ float g_ddiag[(size_t)BATCH * NDIAG * NN];  // D / ln2
__device__ float g_f[(size_t)BATCH * NDIAG * NN];      // forward DP (log2 domain)
__device__ float g_b[(size_t)BATCH * NDIAG * NN];      // backward DP MINUS d (log2)
__device__ float g_max;                                // global logit max (log2)

__device__ __forceinline__ float ex2f(float x) {
    float y; asm("ex2.approx.ftz.f32 %0, %1;" : "=f"(y) : "f"(x)); return y;
}
__device__ __forceinline__ float lg2f(float x) {
    float y; asm("lg2.approx.ftz.f32 %0, %1;" : "=f"(y) : "f"(x)); return y;
}

// ---------------------------------------------------------------------------
// Pre-pass: D (row-major) -> g_ddiag (diag-major), scaled by 1/ln2.
// ---------------------------------------------------------------------------
__global__ void __launch_bounds__(256) diagize_kernel(const float* __restrict__ D) {
    __shared__ float t[32][34];
    int b = blockIdx.z, i0 = blockIdx.y * 32, j0 = blockIdx.x * 32;
    const float* Db = D + (size_t)b * NN * NN;
    float* out = g_ddiag + (size_t)b * NDIAG * NN;
    int tid = threadIdx.x, lane = tid & 31, w = tid >> 5;
#pragma unroll
    for (int r = 0; r < 4; r++) {
        int il = w + 8 * r;
        t[il][lane] = Db[(size_t)(i0 + il) * NN + j0 + lane] * INV_LN2;
    }
    __syncthreads();
#pragma unroll
    for (int r = 0; r < 8; r++) {
        int ld = w + 8 * r;
        if (ld < 63) {
            int ilo = max(0, ld - 31);
            int il = ilo + lane;
            if (il <= min(31, ld)) {
                int k = i0 + j0 + ld;
                out[(size_t)k * NN + (i0 + il)] = t[il][ld - il];
            }
        }
    }
}

__device__ __forceinline__ float lse_cell(float dg, float up, float lf, float dcur) {
    float hi1 = fmaxf(dg, up);
    float lo1 = fminf(dg, up);
    float m   = fmaxf(hi1, lf);
    float o2  = fminf(hi1, lf);
    float s = ex2f(lo1 - m) + ex2f(o2 - m);   // third term is 2^0 = 1
    return dcur + m + lg2f(1.0f + s);
}

// ---------------------------------------------------------------------------
// Wavefront DP, one CTA per (batch, direction): 128 CTAs -> 128 SMs busy.
// 512 threads = one per row i. k-loop unrolled x8 keeps the 8-deep LDG
// prefetch pipeline real; 4 rotating smem buffers keep the selector static.
// Backward CTAs write (val - d) so combine never re-reads d.
// ---------------------------------------------------------------------------
__global__ void __launch_bounds__(512) dp_kernel() {
    __shared__ float bufs[4][TS];      // slot [x][0] is the i=-1 boundary (NEG)
    int bx = blockIdx.x;
    int b = bx >> 1, dir = bx & 1;
    const float* dd = g_ddiag + (size_t)b * NDIAG * NN;
    float* out = (dir ? g_b : g_f) + (size_t)b * NDIAG * NN;

    int i = threadIdx.x;
    if (i < 4) bufs[i][0] = NEGV;
    __syncthreads();

    float pf[8];
#pragma unroll
    for (int q = 0; q < 8; q++) {
        int base = q * NN + i;
        pf[q] = dd[dir ? (CADDR - base) : base];
    }

    for (int t = 0; t < 128; t++) {
#pragma unroll
        for (int p = 0; p < 8; p++) {
            int k = t * 8 + p;                 // k==1023 is a no-op pad
            float dcur = pf[p];
            {
                int kn = k + 8; if (kn > NDIAG - 1) kn = NDIAG - 1;
                int base = kn * NN + i;
                pf[p] = dd[dir ? (CADDR - base) : base];
            }
            if (k < NDIAG) {                   // uniform over the block
                float* bc  = &bufs[p & 3][1];          // diag k
                float* b1p = &bufs[(p + 3) & 3][1];    // diag k-1
                float* b2p = &bufs[(p + 2) & 3][1];    // diag k-2
                int j = k - i;
                if (j >= 0 && j < NN) {
                    float dg = (j == 0) ? ((i == 0) ? 0.0f : NEGV) : b2p[i - 1];
                    float up = b1p[i - 1];             // i==0 -> boundary
                    float lf = (j == 0) ? NEGV : b1p[i];
                    float val = lse_cell(dg, up, lf, dcur);
                    bc[i] = val;
                    out[(size_t)k * NN + i] = dir ? (val - dcur) : val;
                }
                __syncthreads();
            }
        }
    }
}

// ---------------------------------------------------------------------------
// Global max: every path passes through the corner cell, so
// max logit = f(N-1, M-1) maximized over batches. 64 loads, one warp.
// ---------------------------------------------------------------------------
__global__ void max_kernel() {
    int t = threadIdx.x;   // 32 threads
    float m = -3.4e38f;
    for (int b = t; b < BATCH; b += 32)
        m = fmaxf(m, g_f[(size_t)b * NDIAG * NN + (size_t)1022 * NN + 511]);
#pragma unroll
    for (int o = 16; o > 0; o >>= 1)
        m = fmaxf(m, __shfl_xor_sync(0xffffffffu, m, o));
    if (t == 0) g_max = m;
}

// ---------------------------------------------------------------------------
// Combine + finish fused: out = (f2 + (b2-d2) - max2) * ln2, de-diagonalized
// to row-major via a padded smem tile.
// ---------------------------------------------------------------------------
__global__ void __launch_bounds__(256) combine_kernel(float* __restrict__ out) {
    __shared__ float tile[32][257];
    int b = blockIdx.y;
    int k0 = blockIdx.x * 32;
    const float* fd = g_f + (size_t)b * NDIAG * NN;
    const float* bd = g_b + (size_t)b * NDIAG * NN;
    float* ob = out + (size_t)b * NN * NN;
    int tid = threadIdx.x, lane = tid & 31, w = tid >> 5;
    float mx = g_max;

    for (int ih = 0; ih < 2; ih++) {
        int ibase = ih * 256;
        for (int kk = 0; kk < 32; kk++) {
            int k = k0 + kk;
            int i = ibase + tid;
            int j = k - i;
            float v = 0.0f;
            if (j >= 0 && j < NN) {
                int a = k * NN + i;
                v = (fd[a] + bd[(1022 - k) * NN + (511 - i)] - mx) * LN2F;
            }
            tile[kk][tid] = v;
        }
        __syncthreads();
        for (int rr = 0; rr < 32; rr++) {
            int i = ibase + w * 32 + rr;
            int jlo = max(0, k0 - i);
            int jhi = min(NN - 1, k0 + 31 - i);
            int j = jlo + lane;
            if (j <= jhi) {
                int kk = i + j - k0;
                ob[(size_t)i * NN + j] = tile[kk][i - ibase];
            }
        }
        __syncthreads();
    }
}

extern "C" void kernel_launch(void* const* d_in, const int* in_sizes, int n_in,
                              void* d_out, int out_size) {
    const float* d = (const float*)d_in[0];
    float* out = (float*)d_out;

    dim3 dgrid(16, 16, BATCH);
    diagize_kernel<<<dgrid, 256>>>(d);

    dp_kernel<<<BATCH * 2, 512>>>();

    max_kernel<<<1, 32>>>();

    dim3 cgrid(32, BATCH);
    combine_kernel<<<cgrid, 256>>>(out);
}